// round 12
// baseline (speedup 1.0000x reference)
#include <cuda_runtime.h>
#include <math.h>

// Problem dims
#define Bn   64
#define Tn   1024
#define In   128
#define Hn   512
#define HHn  256
#define On   10

// Scan kernel config: 8 batch groups x 16 H-slices = 128 CTAs
#define NG    8
#define NSL   16
#define BPG   8      // batch rows per group
#define JS    32     // H cols per slice
#define MS    16     // HH cols per slice
#define NTHR  256

// SMEM layout (floats), padded to kill bank conflicts
#define WREC_F  (512*33)
#define WT1H_F  (512*17)
#define WT2_F   (256*33)
#define HS_F    (8*512)
#define HID_F   (8*256)
#define RED_F   256
#define SMEM_FLOATS (WREC_F + WT1H_F + WT2_F + HS_F + HID_F + RED_F + 64)
#define SMEM_BYTES  (SMEM_FLOATS * 4)

// Static scratch (no runtime allocation allowed)
__device__ float    g_xh[(size_t)Bn*Tn*Hn];     // xp, overwritten in place by h_t (= hs)
__device__ float    g_xtau[(size_t)Bn*Tn*HHn];  // x @ W_comb + b_comb
__device__ float    g_hid[Bn*HHn];              // per-step tau-hidden exchange
__device__ float    g_Wcomb[In*HHn];
__device__ float    g_bcomb[HHn];
__device__ unsigned g_bar[NG];

__global__ void init_kernel() {
    if (threadIdx.x < NG) g_bar[threadIdx.x] = 0u;
}

// ---------------------------------------------------------------------------
// W_comb = W_in @ W_tau1[:H,:], b_comb = b_in @ W_tau1[:H,:] + b_tau1
// grid = 129 blocks x 256 threads (block 128 does the bias row)
// ---------------------------------------------------------------------------
__global__ void __launch_bounds__(256) wcomb_kernel(
    const float* __restrict__ W_in, const float* __restrict__ b_in,
    const float* __restrict__ W_tau1, const float* __restrict__ b_tau1,
    float* __restrict__ W_comb, float* __restrict__ b_comb)
{
    const int m = threadIdx.x;   // 0..255
    const int i = blockIdx.x;    // 0..128
    if (i < In) {
        float acc = 0.f;
        for (int k = 0; k < Hn; k += 4) {
            float4 a = *(const float4*)(W_in + i * Hn + k);
            acc = fmaf(a.x, W_tau1[(k + 0) * HHn + m], acc);
            acc = fmaf(a.y, W_tau1[(k + 1) * HHn + m], acc);
            acc = fmaf(a.z, W_tau1[(k + 2) * HHn + m], acc);
            acc = fmaf(a.w, W_tau1[(k + 3) * HHn + m], acc);
        }
        W_comb[i * HHn + m] = acc;
    } else {
        float acc = b_tau1[m];
        for (int k = 0; k < Hn; ++k)
            acc = fmaf(b_in[k], W_tau1[k * HHn + m], acc);
        b_comb[m] = acc;
    }
}

// ---------------------------------------------------------------------------
// Tiled fp32 GEMM + bias: C[M,N] = A[M,K] @ Bw[K,N] + bias[N]
// BM=128, BN=64, BK=16, 256 threads, per-thread 8x4. Dims must divide tiles.
// ---------------------------------------------------------------------------
__global__ void __launch_bounds__(256) gemm_bias_kernel(
    const float* __restrict__ A, const float* __restrict__ Bw,
    const float* __restrict__ bias, float* __restrict__ C,
    int M, int N, int K)
{
    __shared__ float As[16][128];
    __shared__ float Bs[16][64];

    const int tid = threadIdx.x;
    const int tx  = tid & 15;
    const int ty  = tid >> 4;
    const int bm  = blockIdx.y * 128;
    const int bn  = blockIdx.x * 64;

    float acc[8][4];
#pragma unroll
    for (int i = 0; i < 8; ++i)
#pragma unroll
        for (int j = 0; j < 4; ++j) acc[i][j] = 0.f;

    const int lar = tid >> 2;
    const int lac = (tid & 3) * 4;
    const int lbr = tid >> 4;
    const int lbc = (tid & 15) * 4;

    for (int k0 = 0; k0 < K; k0 += 16) {
#pragma unroll
        for (int l = 0; l < 2; ++l) {
            int r = lar + l * 64;
            float4 a4 = *(const float4*)&A[(size_t)(bm + r) * K + k0 + lac];
            As[lac + 0][r] = a4.x;
            As[lac + 1][r] = a4.y;
            As[lac + 2][r] = a4.z;
            As[lac + 3][r] = a4.w;
        }
        *(float4*)&Bs[lbr][lbc] = *(const float4*)&Bw[(size_t)(k0 + lbr) * N + bn + lbc];
        __syncthreads();

#pragma unroll
        for (int kk = 0; kk < 16; ++kk) {
            float arv[8], brv[4];
#pragma unroll
            for (int i = 0; i < 8; ++i) arv[i] = As[kk][ty * 8 + i];
#pragma unroll
            for (int j = 0; j < 4; ++j) brv[j] = Bs[kk][tx * 4 + j];
#pragma unroll
            for (int i = 0; i < 8; ++i)
#pragma unroll
                for (int j = 0; j < 4; ++j)
                    acc[i][j] = fmaf(arv[i], brv[j], acc[i][j]);
        }
        __syncthreads();
    }

    float4 bv = *(const float4*)&bias[bn + tx * 4];
#pragma unroll
    for (int i = 0; i < 8; ++i) {
        float4 o;
        o.x = acc[i][0] + bv.x;
        o.y = acc[i][1] + bv.y;
        o.z = acc[i][2] + bv.z;
        o.w = acc[i][3] + bv.w;
        *(float4*)&C[(size_t)(bm + ty * 8 + i) * N + bn + tx * 4] = o;
    }
}

// ---------------------------------------------------------------------------
// Group barrier: 16 CTAs of one batch group, monotonic L2 counter.
// ---------------------------------------------------------------------------
__device__ __forceinline__ void gbar(unsigned* p, unsigned tgt)
{
    __threadfence();          // release this thread's prior stores
    __syncthreads();
    if (threadIdx.x == 0) {
        atomicAdd(p, 1u);
        while (((volatile unsigned*)p)[0] < tgt) { }
        __threadfence();      // acquire
    }
    __syncthreads();
}

// ---------------------------------------------------------------------------
// Persistent scan kernel. 128 CTAs (8 groups x 16 slices), weights SMEM-
// resident, h/hid exchanged through L2 with group barriers.
// ---------------------------------------------------------------------------
__global__ void __launch_bounds__(NTHR, 1) recur_kernel(
    const float* __restrict__ W_rec, const float* __restrict__ bias,
    const float* __restrict__ W_tau1, const float* __restrict__ W_tau2,
    const float* __restrict__ b_tau2)
{
    extern __shared__ float sm[];
    float* Wrec_s = sm;                      // [512][33]  Wrec_s[k][c] = W_rec[js+c, k]
    float* Wt1h_s = Wrec_s + WREC_F;         // [512][17]  Wt1h_s[k][m] = W_tau1[H+k, ms+m]
    float* Wt2_s  = Wt1h_s + WT1H_F;         // [256][33]  Wt2_s[k][c]  = W_tau2[k, js+c]
    float* h_s    = Wt2_s + WT2_F;           // [8][512]
    float* hid_s  = h_s + HS_F;              // [8][256]
    float* red    = hid_s + HID_F;           // [256]
    float* bias_s = red + RED_F;             // [32]
    float* bt2_s  = bias_s + 32;             // [32]

    const int tid  = threadIdx.x;
    const int g    = blockIdx.x >> 4;        // batch group 0..7
    const int sl   = blockIdx.x & 15;        // slice 0..15
    const int js   = sl * JS;
    const int ms   = sl * MS;
    const int bg0  = g * BPG;
    const int lane = tid & 31;
    const int w    = tid >> 5;

    // Output maps. wrec/wt2: warp covers 2 rows x 16 cols, 1 output/thread.
    const int rw = 2 * (w & 3) + (lane >> 4);       // row 0..7
    const int cw = 16 * (w >> 2) + (lane & 15);     // col 0..31
    // wt1h: K split in halves across warp quartets.
    const int kh = (w >> 2) * 256;                  // k offset 0 / 256
    const int rt = rw;                              // row 0..7
    const int mt = lane & 15;                       // m 0..15

    // ---- one-time weight staging ----
    for (int idx = tid; idx < Hn * JS; idx += NTHR) {
        int k = idx & 511, c = idx >> 9;
        Wrec_s[k * 33 + c] = W_rec[(js + c) * Hn + k];
    }
    for (int idx = tid; idx < Hn * MS; idx += NTHR) {
        int m = idx & 15, k = idx >> 4;
        Wt1h_s[k * 17 + m] = W_tau1[(Hn + k) * HHn + ms + m];
    }
    for (int idx = tid; idx < HHn * JS; idx += NTHR) {
        int c = idx & 31, k = idx >> 5;
        Wt2_s[k * 33 + c] = W_tau2[k * Hn + js + c];
    }
    if (tid < 32) {
        bias_s[tid] = bias[js + tid];
        bt2_s[tid]  = b_tau2[js + tid];
    }
    for (int i = tid; i < HS_F; i += NTHR) h_s[i] = 0.f;   // h0 = 0
    __syncthreads();

    unsigned bar_t = 0;
    unsigned* barp = &g_bar[g];

    for (int t = 0; t < Tn; ++t) {
        // prefetch per-step inputs
        float xp_v = __ldg(&g_xh[((bg0 + rw) * Tn + t) * Hn + js + cw]);
        float xtau_v = 0.f;
        if (tid < 128)
            xtau_v = __ldg(&g_xtau[((bg0 + (tid >> 4)) * Tn + t) * HHn + ms + (tid & 15)]);

        // ---- phase A: acc_rec = h @ Wrec_slice ----
        float acc_rec = 0.f;
        {
            const float* hr = h_s + rw * Hn;
#pragma unroll 4
            for (int k0 = 0; k0 < Hn; k0 += 8) {
                float4 ha = *(const float4*)(hr + k0);
                float4 hb = *(const float4*)(hr + k0 + 4);
                acc_rec = fmaf(ha.x, Wrec_s[(k0 + 0) * 33 + cw], acc_rec);
                acc_rec = fmaf(ha.y, Wrec_s[(k0 + 1) * 33 + cw], acc_rec);
                acc_rec = fmaf(ha.z, Wrec_s[(k0 + 2) * 33 + cw], acc_rec);
                acc_rec = fmaf(ha.w, Wrec_s[(k0 + 3) * 33 + cw], acc_rec);
                acc_rec = fmaf(hb.x, Wrec_s[(k0 + 4) * 33 + cw], acc_rec);
                acc_rec = fmaf(hb.y, Wrec_s[(k0 + 5) * 33 + cw], acc_rec);
                acc_rec = fmaf(hb.z, Wrec_s[(k0 + 6) * 33 + cw], acc_rec);
                acc_rec = fmaf(hb.w, Wrec_s[(k0 + 7) * 33 + cw], acc_rec);
            }
        }

        // ---- phase A: wt1h partial (K halves), reduce, relu, publish hid ----
        {
            float part = 0.f;
            const float* hr = h_s + rt * Hn;
#pragma unroll 4
            for (int k0 = kh; k0 < kh + 256; k0 += 8) {
                float4 ha = *(const float4*)(hr + k0);
                float4 hb = *(const float4*)(hr + k0 + 4);
                part = fmaf(ha.x, Wt1h_s[(k0 + 0) * 17 + mt], part);
                part = fmaf(ha.y, Wt1h_s[(k0 + 1) * 17 + mt], part);
                part = fmaf(ha.z, Wt1h_s[(k0 + 2) * 17 + mt], part);
                part = fmaf(ha.w, Wt1h_s[(k0 + 3) * 17 + mt], part);
                part = fmaf(hb.x, Wt1h_s[(k0 + 4) * 17 + mt], part);
                part = fmaf(hb.y, Wt1h_s[(k0 + 5) * 17 + mt], part);
                part = fmaf(hb.z, Wt1h_s[(k0 + 6) * 17 + mt], part);
                part = fmaf(hb.w, Wt1h_s[(k0 + 7) * 17 + mt], part);
            }
            red[(w >> 2) * 128 + rt * 16 + mt] = part;
        }
        __syncthreads();
        if (tid < 128) {
            float s = red[tid] + red[128 + tid];
            float hv = fmaxf(s + xtau_v, 0.f);
            g_hid[(bg0 + (tid >> 4)) * HHn + ms + (tid & 15)] = hv;
        }

        bar_t += NSL;
        gbar(barp, bar_t);

        // stage full hid [8][256]
        {
#pragma unroll
            for (int i = 0; i < 2; ++i) {
                int f = i * NTHR + tid;       // 0..511 float4 index
                int row = f >> 6, k4 = f & 63;
                float4 v = __ldcg((const float4*)(g_hid + (bg0 + row) * HHn) + k4);
                *(float4*)(hid_s + row * HHn + k4 * 4) = v;
            }
        }
        __syncthreads();

        // ---- phase B: tau, drive, Euler update ----
        float tpre = 0.f;
        {
            const float* hr = hid_s + rw * HHn;
#pragma unroll 4
            for (int k0 = 0; k0 < HHn; k0 += 8) {
                float4 ha = *(const float4*)(hr + k0);
                float4 hb = *(const float4*)(hr + k0 + 4);
                tpre = fmaf(ha.x, Wt2_s[(k0 + 0) * 33 + cw], tpre);
                tpre = fmaf(ha.y, Wt2_s[(k0 + 1) * 33 + cw], tpre);
                tpre = fmaf(ha.z, Wt2_s[(k0 + 2) * 33 + cw], tpre);
                tpre = fmaf(ha.w, Wt2_s[(k0 + 3) * 33 + cw], tpre);
                tpre = fmaf(hb.x, Wt2_s[(k0 + 4) * 33 + cw], tpre);
                tpre = fmaf(hb.y, Wt2_s[(k0 + 5) * 33 + cw], tpre);
                tpre = fmaf(hb.z, Wt2_s[(k0 + 6) * 33 + cw], tpre);
                tpre = fmaf(hb.w, Wt2_s[(k0 + 7) * 33 + cw], tpre);
            }
        }
        tpre += bt2_s[cw];
        float sg   = 1.0f / (1.0f + expf(-tpre));
        float tau  = 5.0f + 45.0f * sg;
        float drv  = tanhf(xp_v + acc_rec + bias_s[cw]);
        float hold = h_s[rw * Hn + js + cw];
        float hnew = hold + (drv - hold) / tau;
        g_xh[((bg0 + rw) * Tn + t) * Hn + js + cw] = hnew;   // hs output + exchange

        bar_t += NSL;
        gbar(barp, bar_t);

        // reload full h [8][512]
        {
#pragma unroll
            for (int i = 0; i < 4; ++i) {
                int f = i * NTHR + tid;       // 0..1023 float4 index
                int row = f >> 7, k4 = f & 127;
                float4 v = __ldcg((const float4*)(g_xh + ((bg0 + row) * Tn + t) * Hn) + k4);
                *(float4*)(h_s + row * Hn + k4 * 4) = v;
            }
        }
        __syncthreads();
    }
}

// ---------------------------------------------------------------------------
// out[r, :] = hs[r, :] @ W_out + b_out ; one warp per row, N=10
// ---------------------------------------------------------------------------
__global__ void __launch_bounds__(256) out_kernel(
    const float* __restrict__ hs, const float* __restrict__ W_out,
    const float* __restrict__ b_out, float* __restrict__ out)
{
    __shared__ float Ws[Hn * 11];
    __shared__ float bo[On];
    const int tid = threadIdx.x;
    for (int idx = tid; idx < Hn * On; idx += 256) {
        int k = idx / On, j = idx - k * On;
        Ws[k * 11 + j] = W_out[idx];
    }
    if (tid < On) bo[tid] = b_out[tid];
    __syncthreads();

    const int lane = tid & 31;
    const int wrp  = tid >> 5;
    const int row  = blockIdx.x * 8 + wrp;
    const float* hr = hs + (size_t)row * Hn;

    float a[On];
#pragma unroll
    for (int j = 0; j < On; ++j) a[j] = 0.f;

#pragma unroll
    for (int kk = 0; kk < 16; ++kk) {
        int k = kk * 32 + lane;
        float h = __ldg(hr + k);
#pragma unroll
        for (int j = 0; j < On; ++j) a[j] = fmaf(h, Ws[k * 11 + j], a[j]);
    }
#pragma unroll
    for (int j = 0; j < On; ++j) {
#pragma unroll
        for (int off = 16; off > 0; off >>= 1)
            a[j] += __shfl_xor_sync(0xffffffffu, a[j], off);
    }
    if (lane == 0) {
#pragma unroll
        for (int j = 0; j < On; ++j)
            out[(size_t)row * On + j] = a[j] + bo[j];
    }
}

// ---------------------------------------------------------------------------
extern "C" void kernel_launch(void* const* d_in, const int* in_sizes, int n_in,
                              void* d_out, int out_size)
{
    const float* x      = (const float*)d_in[0];
    const float* W_in   = (const float*)d_in[1];
    const float* b_in   = (const float*)d_in[2];
    const float* W_rec  = (const float*)d_in[3];
    const float* bias   = (const float*)d_in[4];
    const float* W_tau1 = (const float*)d_in[5];
    const float* b_tau1 = (const float*)d_in[6];
    const float* W_tau2 = (const float*)d_in[7];
    const float* b_tau2 = (const float*)d_in[8];
    const float* W_out  = (const float*)d_in[9];
    const float* b_out  = (const float*)d_in[10];
    float* out = (float*)d_out;

    float *xh, *xtau, *wcomb, *bcomb;
    cudaGetSymbolAddress((void**)&xh,    g_xh);
    cudaGetSymbolAddress((void**)&xtau,  g_xtau);
    cudaGetSymbolAddress((void**)&wcomb, g_Wcomb);
    cudaGetSymbolAddress((void**)&bcomb, g_bcomb);

    cudaFuncSetAttribute(recur_kernel,
                         cudaFuncAttributeMaxDynamicSharedMemorySize, SMEM_BYTES);

    init_kernel<<<1, 32>>>();
    wcomb_kernel<<<In + 1, 256>>>(W_in, b_in, W_tau1, b_tau1, wcomb, bcomb);
    // xp = x @ W_in + b_in        -> g_xh   [65536, 512]
    gemm_bias_kernel<<<dim3(Hn / 64, (Bn * Tn) / 128), 256>>>(x, W_in, b_in, xh,
                                                              Bn * Tn, Hn, In);
    // xtau = x @ W_comb + b_comb  -> g_xtau [65536, 256]
    gemm_bias_kernel<<<dim3(HHn / 64, (Bn * Tn) / 128), 256>>>(x, wcomb, bcomb, xtau,
                                                               Bn * Tn, HHn, In);
    recur_kernel<<<NG * NSL, NTHR, SMEM_BYTES>>>(W_rec, bias, W_tau1, W_tau2, b_tau2);
    out_kernel<<<(Bn * Tn) / 8, 256>>>(xh, W_out, b_out, out);
}

// round 13
// speedup vs baseline: 1.4983x; 1.4983x over previous
#include <cuda_runtime.h>
#include <math.h>

// Problem dims
#define Bn   64
#define Tn   1024
#define In   128
#define Hn   512
#define HHn  256
#define On   10

// Scan config: 8 batch groups x 16 H-slices = 128 CTAs
#define NG    8
#define NSL   16
#define BPG   8      // batch rows per group
#define JS    32     // H cols per slice
#define MS    16     // HH cols per slice
#define NTHR  256

// SMEM layout (floats)
#define WREC_F   (512*32)      // Wrec_s[k][c]  (c conflict-free, stride 32)
#define WT1H_F   (512*17)      // Wt1h_s[k][m]  (pad 17)
#define WT2_F    (256*32)      // Wt2_s[k][c]
#define HS_F     (512*8)       // h_s[k][r]   pair-packed
#define HID_F    (256*8)       // hid_s[k][r]
#define RED_F    2304          // max(8*288, 16*144)
#define SMEM_FLOATS (WREC_F + WT1H_F + WT2_F + HS_F + HID_F + RED_F + 64)
#define SMEM_BYTES  (SMEM_FLOATS * 4)

typedef unsigned long long ull;

// Static scratch
__device__ float    g_xh[(size_t)Bn*Tn*Hn];     // xp in, hs out (in-place)
__device__ float    g_xtau[(size_t)Bn*Tn*HHn];  // x @ W_comb + b_comb
__device__ float    g_hx[NG*512*8];             // h exchange, k-major pair-packed
__device__ float    g_hidx[NG*256*8];           // hid exchange, k-major pair-packed
__device__ float    g_Wcomb[In*HHn];
__device__ float    g_bcomb[HHn];
__device__ unsigned g_bar[NG];

__global__ void init_kernel() {
    if (threadIdx.x < NG) g_bar[threadIdx.x] = 0u;
}

// ---------------------------------------------------------------------------
// f32x2 packed helpers (FFMA2 — only reachable via PTX fma.rn.f32x2)
// ---------------------------------------------------------------------------
__device__ __forceinline__ ull ffma2(ull a, ull b, ull c) {
    ull d;
    asm("fma.rn.f32x2 %0, %1, %2, %3;" : "=l"(d) : "l"(a), "l"(b), "l"(c));
    return d;
}
__device__ __forceinline__ ull splat2(float w) {
    ull d;
    asm("mov.b64 %0, {%1, %1};" : "=l"(d) : "f"(w));
    return d;
}
__device__ __forceinline__ float2 unpk(ull v) {
    float2 r;
    asm("mov.b64 {%0, %1}, %2;" : "=f"(r.x), "=f"(r.y) : "l"(v));
    return r;
}

// ---------------------------------------------------------------------------
// W_comb = W_in @ W_tau1[:H,:], b_comb = b_in @ W_tau1[:H,:] + b_tau1
// ---------------------------------------------------------------------------
__global__ void __launch_bounds__(256) wcomb_kernel(
    const float* __restrict__ W_in, const float* __restrict__ b_in,
    const float* __restrict__ W_tau1, const float* __restrict__ b_tau1,
    float* __restrict__ W_comb, float* __restrict__ b_comb)
{
    const int m = threadIdx.x;
    const int i = blockIdx.x;
    if (i < In) {
        float acc = 0.f;
        for (int k = 0; k < Hn; k += 4) {
            float4 a = *(const float4*)(W_in + i * Hn + k);
            acc = fmaf(a.x, W_tau1[(k + 0) * HHn + m], acc);
            acc = fmaf(a.y, W_tau1[(k + 1) * HHn + m], acc);
            acc = fmaf(a.z, W_tau1[(k + 2) * HHn + m], acc);
            acc = fmaf(a.w, W_tau1[(k + 3) * HHn + m], acc);
        }
        W_comb[i * HHn + m] = acc;
    } else {
        float acc = b_tau1[m];
        for (int k = 0; k < Hn; ++k)
            acc = fmaf(b_in[k], W_tau1[k * HHn + m], acc);
        b_comb[m] = acc;
    }
}

// ---------------------------------------------------------------------------
// Tiled fp32 GEMM + bias (precompute): C[M,N] = A[M,K] @ Bw[K,N] + bias
// ---------------------------------------------------------------------------
__global__ void __launch_bounds__(256) gemm_bias_kernel(
    const float* __restrict__ A, const float* __restrict__ Bw,
    const float* __restrict__ bias, float* __restrict__ C,
    int M, int N, int K)
{
    __shared__ float As[16][128];
    __shared__ float Bs[16][64];

    const int tid = threadIdx.x;
    const int tx  = tid & 15;
    const int ty  = tid >> 4;
    const int bm  = blockIdx.y * 128;
    const int bn  = blockIdx.x * 64;

    float acc[8][4];
#pragma unroll
    for (int i = 0; i < 8; ++i)
#pragma unroll
        for (int j = 0; j < 4; ++j) acc[i][j] = 0.f;

    const int lar = tid >> 2;
    const int lac = (tid & 3) * 4;
    const int lbr = tid >> 4;
    const int lbc = (tid & 15) * 4;

    for (int k0 = 0; k0 < K; k0 += 16) {
#pragma unroll
        for (int l = 0; l < 2; ++l) {
            int r = lar + l * 64;
            float4 a4 = *(const float4*)&A[(size_t)(bm + r) * K + k0 + lac];
            As[lac + 0][r] = a4.x;
            As[lac + 1][r] = a4.y;
            As[lac + 2][r] = a4.z;
            As[lac + 3][r] = a4.w;
        }
        *(float4*)&Bs[lbr][lbc] = *(const float4*)&Bw[(size_t)(k0 + lbr) * N + bn + lbc];
        __syncthreads();

#pragma unroll
        for (int kk = 0; kk < 16; ++kk) {
            float arv[8], brv[4];
#pragma unroll
            for (int i = 0; i < 8; ++i) arv[i] = As[kk][ty * 8 + i];
#pragma unroll
            for (int j = 0; j < 4; ++j) brv[j] = Bs[kk][tx * 4 + j];
#pragma unroll
            for (int i = 0; i < 8; ++i)
#pragma unroll
                for (int j = 0; j < 4; ++j)
                    acc[i][j] = fmaf(arv[i], brv[j], acc[i][j]);
        }
        __syncthreads();
    }

    float4 bv = *(const float4*)&bias[bn + tx * 4];
#pragma unroll
    for (int i = 0; i < 8; ++i) {
        float4 o;
        o.x = acc[i][0] + bv.x;
        o.y = acc[i][1] + bv.y;
        o.z = acc[i][2] + bv.z;
        o.w = acc[i][3] + bv.w;
        *(float4*)&C[(size_t)(bm + ty * 8 + i) * N + bn + tx * 4] = o;
    }
}

// ---------------------------------------------------------------------------
// Persistent scan kernel. 128 CTAs (8 groups x 16 slices). Weights SMEM-
// resident; 8-row register tile with packed f32x2 FFMA; h/hid exchanged
// through L2 in pair-packed layout with split arrive/wait group barriers.
// ---------------------------------------------------------------------------
__global__ void __launch_bounds__(NTHR, 1) recur_kernel(
    const float* __restrict__ W_rec, const float* __restrict__ bias,
    const float* __restrict__ W_tau1, const float* __restrict__ W_tau2,
    const float* __restrict__ b_tau2)
{
    extern __shared__ float sm[];
    float* Wrec_s = sm;                      // [512][32]  Wrec_s[k*32+c] = W_rec[js+c, k]
    float* Wt1h_s = Wrec_s + WREC_F;         // [512][17]  Wt1h_s[k*17+m] = W_tau1[H+k, ms+m]
    float* Wt2_s  = Wt1h_s + WT1H_F;         // [256][32]  Wt2_s[k*32+c]  = W_tau2[k, js+c]
    float* h_s    = Wt2_s + WT2_F;           // [512][8]   pair-packed
    float* hid_s  = h_s + HS_F;              // [256][8]
    float* red    = hid_s + HID_F;           // [2304]
    float* bias_s = red + RED_F;             // [32]
    float* bt2_s  = bias_s + 32;             // [32]

    const int tid  = threadIdx.x;
    const int g    = blockIdx.x >> 4;
    const int sl   = blockIdx.x & 15;
    const int js   = sl * JS;
    const int ms   = sl * MS;
    const int bg0  = g * BPG;

    // phase thread maps
    const int c8  = tid & 31;                 // col for rec/wt2 (kc = tid>>5, 0..7)
    const int kc8 = tid >> 5;
    const int m16  = tid & 15;                // m for wt1h (kc16 = tid>>4, 0..15)
    const int kc16 = tid >> 4;
    // owner map for the 256 outputs (r, c)
    const int r_o = tid >> 5;                 // 0..7
    const int c_o = tid & 31;                 // 0..31
    // owner map for the 128 hid values (r, m)
    const int r_h = tid >> 4;                 // 0..7 (valid tid<128)
    const int m_h = tid & 15;

    // ---- one-time weight staging ----
    for (int idx = tid; idx < Hn * JS; idx += NTHR) {
        int c = idx & 31, k = idx >> 5;
        Wrec_s[k * 32 + c] = W_rec[(js + c) * Hn + k];
    }
    for (int idx = tid; idx < Hn * MS; idx += NTHR) {
        int m = idx & 15, k = idx >> 4;
        Wt1h_s[k * 17 + m] = W_tau1[(Hn + k) * HHn + ms + m];
    }
    for (int idx = tid; idx < HHn * JS; idx += NTHR) {
        int c = idx & 31, k = idx >> 5;
        Wt2_s[k * 32 + c] = W_tau2[k * Hn + js + c];
    }
    if (tid < 32) {
        bias_s[tid] = bias[js + tid];
        bt2_s[tid]  = b_tau2[js + tid];
    }
    for (int i = tid; i < HS_F; i += NTHR) h_s[i] = 0.f;   // h0 = 0
    __syncthreads();

    unsigned tgt = 0;
    unsigned* barp = &g_bar[g];
    float* hx   = g_hx   + g * (512 * 8);
    float* hidx = g_hidx + g * (256 * 8);

    for (int t = 0; t < Tn; ++t) {
        // prefetch per-step inputs
        float xp_v = __ldg(&g_xh[((size_t)(bg0 + r_o) * Tn + t) * Hn + js + c_o]);
        float xtau_v = 0.f;
        if (tid < 128)
            xtau_v = __ldg(&g_xtau[((size_t)(bg0 + r_h) * Tn + t) * HHn + ms + m_h]);

        // ---- wt1h partials: thread (m16, kc16), 32 k each, 8 rows packed ----
        {
            const float* wp = Wt1h_s + (kc16 * 32) * 17 + m16;
            const float* hp = h_s + (kc16 * 32) * 8;
            ull a01 = 0, a23 = 0, a45 = 0, a67 = 0;
#pragma unroll 8
            for (int j = 0; j < 32; ++j) {
                ull w2 = splat2(wp[j * 17]);
                ulonglong2 p0 = *(const ulonglong2*)(hp + j * 8);
                ulonglong2 p1 = *(const ulonglong2*)(hp + j * 8 + 4);
                a01 = ffma2(w2, p0.x, a01);
                a23 = ffma2(w2, p0.y, a23);
                a45 = ffma2(w2, p1.x, a45);
                a67 = ffma2(w2, p1.y, a67);
            }
            float* rb = red + kc16 * 144 + m16 * 9;
            float2 q0 = unpk(a01), q1 = unpk(a23), q2 = unpk(a45), q3 = unpk(a67);
            rb[0] = q0.x; rb[1] = q0.y; rb[2] = q1.x; rb[3] = q1.y;
            rb[4] = q2.x; rb[5] = q2.y; rb[6] = q3.x; rb[7] = q3.y;
        }
        __syncthreads();
        if (tid < 128) {
            float s = xtau_v;
#pragma unroll
            for (int kc = 0; kc < 16; ++kc)
                s += red[kc * 144 + m_h * 9 + r_h];
            float hv = fmaxf(s, 0.f);
            hidx[(ms + m_h) * 8 + r_h] = hv;
            __threadfence();
        }
        __syncthreads();
        if (tid == 0) atomicAdd(barp, 1u);           // arrive bar1
        tgt += NSL;

        // ---- rec partials: thread (c8, kc8), 64 k each (hides bar1) ----
        {
            const float* wp = Wrec_s + (kc8 * 64) * 32 + c8;
            const float* hp = h_s + (kc8 * 64) * 8;
            ull a01 = 0, a23 = 0, a45 = 0, a67 = 0;
#pragma unroll 8
            for (int j = 0; j < 64; ++j) {
                ull w2 = splat2(wp[j * 32]);
                ulonglong2 p0 = *(const ulonglong2*)(hp + j * 8);
                ulonglong2 p1 = *(const ulonglong2*)(hp + j * 8 + 4);
                a01 = ffma2(w2, p0.x, a01);
                a23 = ffma2(w2, p0.y, a23);
                a45 = ffma2(w2, p1.x, a45);
                a67 = ffma2(w2, p1.y, a67);
            }
            float* rb = red + kc8 * 288 + c8 * 9;
            float2 q0 = unpk(a01), q1 = unpk(a23), q2 = unpk(a45), q3 = unpk(a67);
            rb[0] = q0.x; rb[1] = q0.y; rb[2] = q1.x; rb[3] = q1.y;
            rb[4] = q2.x; rb[5] = q2.y; rb[6] = q3.x; rb[7] = q3.y;
        }
        __syncthreads();
        float acc_rec = 0.f;
#pragma unroll
        for (int kc = 0; kc < 8; ++kc)
            acc_rec += red[kc * 288 + c_o * 9 + r_o];

        if (tid == 0) {                               // wait bar1
            while (((volatile unsigned*)barp)[0] < tgt) { }
            __threadfence();
        }
        __syncthreads();

        // stage hid (coalesced, pair-packed already)
#pragma unroll
        for (int i = 0; i < 2; ++i) {
            int f = i * NTHR + tid;                   // 512 float4
            float4 v = __ldcg((const float4*)hidx + f);
            *(float4*)(hid_s + f * 4) = v;
        }
        __syncthreads();

        // ---- wt2 partials: thread (c8, kc8), 32 k each ----
        {
            const float* wp = Wt2_s + (kc8 * 32) * 32 + c8;
            const float* hp = hid_s + (kc8 * 32) * 8;
            ull a01 = 0, a23 = 0, a45 = 0, a67 = 0;
#pragma unroll 8
            for (int j = 0; j < 32; ++j) {
                ull w2 = splat2(wp[j * 32]);
                ulonglong2 p0 = *(const ulonglong2*)(hp + j * 8);
                ulonglong2 p1 = *(const ulonglong2*)(hp + j * 8 + 4);
                a01 = ffma2(w2, p0.x, a01);
                a23 = ffma2(w2, p0.y, a23);
                a45 = ffma2(w2, p1.x, a45);
                a67 = ffma2(w2, p1.y, a67);
            }
            float* rb = red + kc8 * 288 + c8 * 9;
            float2 q0 = unpk(a01), q1 = unpk(a23), q2 = unpk(a45), q3 = unpk(a67);
            rb[0] = q0.x; rb[1] = q0.y; rb[2] = q1.x; rb[3] = q1.y;
            rb[4] = q2.x; rb[5] = q2.y; rb[6] = q3.x; rb[7] = q3.y;
        }
        __syncthreads();

        // ---- epilogue: tau, drive, Euler update, publish ----
        {
            float tpre = bt2_s[c_o];
#pragma unroll
            for (int kc = 0; kc < 8; ++kc)
                tpre += red[kc * 288 + c_o * 9 + r_o];
            float sg   = 1.0f / (1.0f + expf(-tpre));
            float tau  = 5.0f + 45.0f * sg;
            float drv  = tanhf(xp_v + acc_rec + bias_s[c_o]);
            float hold = h_s[(js + c_o) * 8 + r_o];
            float hnew = hold + (drv - hold) / tau;
            g_xh[((size_t)(bg0 + r_o) * Tn + t) * Hn + js + c_o] = hnew;  // hs out
            hx[(js + c_o) * 8 + r_o] = hnew;                              // exchange
            __threadfence();
        }
        __syncthreads();
        if (tid == 0) atomicAdd(barp, 1u);           // arrive bar2
        tgt += NSL;
        if (tid == 0) {                               // wait bar2
            while (((volatile unsigned*)barp)[0] < tgt) { }
            __threadfence();
        }
        __syncthreads();

        // stage full h (coalesced, pair-packed)
#pragma unroll
        for (int i = 0; i < 4; ++i) {
            int f = i * NTHR + tid;                   // 1024 float4
            float4 v = __ldcg((const float4*)hx + f);
            *(float4*)(h_s + f * 4) = v;
        }
        __syncthreads();
    }
}

// ---------------------------------------------------------------------------
// out[r, :] = hs[r, :] @ W_out + b_out ; one warp per row
// ---------------------------------------------------------------------------
__global__ void __launch_bounds__(256) out_kernel(
    const float* __restrict__ hs, const float* __restrict__ W_out,
    const float* __restrict__ b_out, float* __restrict__ out)
{
    __shared__ float Ws[Hn * 11];
    __shared__ float bo[On];
    const int tid = threadIdx.x;
    for (int idx = tid; idx < Hn * On; idx += 256) {
        int k = idx / On, j = idx - k * On;
        Ws[k * 11 + j] = W_out[idx];
    }
    if (tid < On) bo[tid] = b_out[tid];
    __syncthreads();

    const int lane = tid & 31;
    const int wrp  = tid >> 5;
    const int row  = blockIdx.x * 8 + wrp;
    const float* hr = hs + (size_t)row * Hn;

    float a[On];
#pragma unroll
    for (int j = 0; j < On; ++j) a[j] = 0.f;

#pragma unroll
    for (int kk = 0; kk < 16; ++kk) {
        int k = kk * 32 + lane;
        float h = __ldg(hr + k);
#pragma unroll
        for (int j = 0; j < On; ++j) a[j] = fmaf(h, Ws[k * 11 + j], a[j]);
    }
#pragma unroll
    for (int j = 0; j < On; ++j) {
#pragma unroll
        for (int off = 16; off > 0; off >>= 1)
            a[j] += __shfl_xor_sync(0xffffffffu, a[j], off);
    }
    if (lane == 0) {
#pragma unroll
        for (int j = 0; j < On; ++j)
            out[(size_t)row * On + j] = a[j] + bo[j];
    }
}

// ---------------------------------------------------------------------------
extern "C" void kernel_launch(void* const* d_in, const int* in_sizes, int n_in,
                              void* d_out, int out_size)
{
    const float* x      = (const float*)d_in[0];
    const float* W_in   = (const float*)d_in[1];
    const float* b_in   = (const float*)d_in[2];
    const float* W_rec  = (const float*)d_in[3];
    const float* bias   = (const float*)d_in[4];
    const float* W_tau1 = (const float*)d_in[5];
    const float* b_tau1 = (const float*)d_in[6];
    const float* W_tau2 = (const float*)d_in[7];
    const float* b_tau2 = (const float*)d_in[8];
    const float* W_out  = (const float*)d_in[9];
    const float* b_out  = (const float*)d_in[10];
    float* out = (float*)d_out;

    float *xh, *xtau, *wcomb, *bcomb;
    cudaGetSymbolAddress((void**)&xh,    g_xh);
    cudaGetSymbolAddress((void**)&xtau,  g_xtau);
    cudaGetSymbolAddress((void**)&wcomb, g_Wcomb);
    cudaGetSymbolAddress((void**)&bcomb, g_bcomb);

    cudaFuncSetAttribute(recur_kernel,
                         cudaFuncAttributeMaxDynamicSharedMemorySize, SMEM_BYTES);

    init_kernel<<<1, 32>>>();
    wcomb_kernel<<<In + 1, 256>>>(W_in, b_in, W_tau1, b_tau1, wcomb, bcomb);
    gemm_bias_kernel<<<dim3(Hn / 64, (Bn * Tn) / 128), 256>>>(x, W_in, b_in, xh,
                                                              Bn * Tn, Hn, In);
    gemm_bias_kernel<<<dim3(HHn / 64, (Bn * Tn) / 128), 256>>>(x, wcomb, bcomb, xtau,
                                                               Bn * Tn, HHn, In);
    recur_kernel<<<NG * NSL, NTHR, SMEM_BYTES>>>(W_rec, bias, W_tau1, W_tau2, b_tau2);
    out_kernel<<<(Bn * Tn) / 8, 256>>>(xh, W_out, b_out, out);
}